// round 4
// baseline (speedup 1.0000x reference)
#include <cuda_runtime.h>

#define IMG 512
#define TW 64
#define TH 32
#define KS 11
#define HALO 5
#define COLS 74              /* TW + 2*HALO */
#define S2 75                /* row stride (odd -> conflict-free) */
#define RG 4                 /* output rows per vertical task */
#define NROWG (TH/RG)        /* 8 */
#define NTASK (COLS*NROWG)   /* 592 */
#define NTHREADS 256
#define NSLOTS 128
#define SMEM_BYTES (TH*S2*8*2 + TH*S2*4)   /* 48000 B -> 4 CTAs/SM */

typedef unsigned long long u64;

__device__ double g_slots[NSLOTS];   /* zero-init at load; finalize re-zeros each replay */

__device__ __forceinline__ u64 pack2(float x, float y) {
    u64 r; asm("mov.b64 %0, {%1,%2};" : "=l"(r) : "f"(x), "f"(y)); return r;
}
__device__ __forceinline__ void unpack2(u64 v, float& x, float& y) {
    asm("mov.b64 {%0,%1}, %2;" : "=f"(x), "=f"(y) : "l"(v));
}
__device__ __forceinline__ u64 fma2(u64 a, u64 b, u64 c) {
    u64 d; asm("fma.rn.f32x2 %0, %1, %2, %3;" : "=l"(d) : "l"(a), "l"(b), "l"(c)); return d;
}
__device__ __forceinline__ u64 mul2(u64 a, u64 b) {
    u64 d; asm("mul.rn.f32x2 %0, %1, %2;" : "=l"(d) : "l"(a), "l"(b)); return d;
}

/* Gaussian symmetry w[k] == w[10-k] (bit-exact: k2 = g outer g) */
#define WIDX(k) ((k) < 6 ? (k) : 10 - (k))

extern __shared__ float2 smem_dyn[];

template<bool SAFE>
__device__ __forceinline__ void vtask(const float* __restrict__ xb,
                                      const float* __restrict__ yb,
                                      int r0, bool colok,
                                      const u64* __restrict__ wv2,
                                      u64* a1, u64* a2, float* a3) {
    #pragma unroll
    for (int tt = 0; tt < RG + KS - 1; tt++) {   // 14 input rows
        float vx, vy;
        if (SAFE) {
            vx = 0.f; vy = 0.f;
            int gr = r0 + tt;
            if (colok && (unsigned)gr < (unsigned)IMG) {
                vx = __ldg(xb + tt * IMG);
                vy = __ldg(yb + tt * IMG);
            }
        } else {
            vx = __ldg(xb + tt * IMG);
            vy = __ldg(yb + tt * IMG);
        }
        u64 u = pack2(vx, vy);
        u64 v = mul2(u, u);
        float pxy = vx * vy;
        #pragma unroll
        for (int i = 0; i < RG; i++) {
            int k = tt - i;
            if (k >= 0 && k < KS) {
                int wi = WIDX(k);
                a1[i] = fma2(wv2[wi], u, a1[i]);
                a2[i] = fma2(wv2[wi], v, a2[i]);
                a3[i] = fmaf(__uint_as_float((unsigned)(wv2[wi] & 0xffffffffull)), pxy, a3[i]);
            }
        }
    }
}

__global__ __launch_bounds__(NTHREADS, 4)
void ssim_main(const float* __restrict__ x, const float* __restrict__ y,
               const float* __restrict__ kern) {
    float2* s_v1 = smem_dyn;                 // [TH][S2] (sx,sy)
    float2* s_v2 = s_v1 + TH * S2;           // [TH][S2] (sxx,syy)
    float*  s_v3 = (float*)(s_v2 + TH * S2); // [TH][S2] sxy
    __shared__ float s_wraw[22];

    const int tid = threadIdx.x;
    const int plane = blockIdx.z;            // 64 = 32 batch * 2 chan (NCHW)
    const int ch = plane & 1;
    const int oh0 = blockIdx.y * TH;
    const int ow0 = blockIdx.x * TW;
    const float* xp = x + (size_t)plane * IMG * IMG;
    const float* yp = y + (size_t)plane * IMG * IMG;

    // ---- weights: rank-1 factors from 2D gaussian, 22 threads ----
    if (tid < 22) {
        const float* kc = kern + ch * KS * KS;
        float s = 0.f;
        if (tid < KS) {
            #pragma unroll
            for (int j = 0; j < KS; j++) s += kc[tid * KS + j];       // row sums
        } else {
            #pragma unroll
            for (int j = 0; j < KS; j++) s += kc[j * KS + tid - KS];  // col sums
        }
        s_wraw[tid] = s;
    }
    __syncthreads();

    u64 wv2[6];
    {
        #pragma unroll
        for (int k = 0; k < 6; k++) { float w = s_wraw[k]; wv2[k] = pack2(w, w); }
    }

    // ---- stage 1: vertical conv straight from global ----
    for (int t = tid; t < NTASK; t += NTHREADS) {
        int rgi = t / COLS;
        int col = t - rgi * COLS;
        int rg = rgi * RG;
        int gc = ow0 + col - HALO;
        bool colok = (unsigned)gc < (unsigned)IMG;
        int r0 = oh0 + rg - HALO;
        const float* xb = xp + (ptrdiff_t)r0 * IMG + gc;
        const float* yb = yp + (ptrdiff_t)r0 * IMG + gc;

        u64 a1[RG], a2[RG]; float a3[RG];
        #pragma unroll
        for (int i = 0; i < RG; i++) { a1[i] = 0ull; a2[i] = 0ull; a3[i] = 0.f; }

        if (colok && r0 >= 0 && r0 + RG + KS - 2 < IMG) {
            vtask<false>(xb, yb, r0, colok, wv2, a1, a2, a3);
        } else {
            vtask<true>(xb, yb, r0, colok, wv2, a1, a2, a3);
        }

        #pragma unroll
        for (int i = 0; i < RG; i++) {
            *reinterpret_cast<u64*>(&s_v1[(rg + i) * S2 + col]) = a1[i];
            *reinterpret_cast<u64*>(&s_v2[(rg + i) * S2 + col]) = a2[i];
            s_v3[(rg + i) * S2 + col] = a3[i];
        }
    }

    __syncthreads();

    // ---- stage 2: horizontal conv, two half-tasks of 4 px ----
    u64 wh2[6]; float whs[6];
    {
        float T = 0.f;
        #pragma unroll
        for (int k = 0; k < KS; k++) T += s_wraw[k];
        float invT = 1.0f / T;
        #pragma unroll
        for (int k = 0; k < 6; k++) {
            float w = s_wraw[11 + k] * invT;
            whs[k] = w; wh2[k] = pack2(w, w);
        }
    }

    const int row = tid & 31;      // lanes span rows -> odd stride, conflict-free
    const int c0 = (tid >> 5) * 8;
    const float C1 = 1e-4f, C2 = 9e-4f;
    float lsum = 0.f;

    #pragma unroll
    for (int ph = 0; ph < 2; ph++) {
        int cb = c0 + 4 * ph;
        u64 h1[4], h2[4]; float h3[4];
        #pragma unroll
        for (int p = 0; p < 4; p++) { h1[p] = 0ull; h2[p] = 0ull; h3[p] = 0.f; }

        #pragma unroll
        for (int j = 0; j < RG + KS - 1; j++) {      // 14 input cols
            u64 b1 = *reinterpret_cast<const u64*>(&s_v1[row * S2 + cb + j]);
            u64 b2 = *reinterpret_cast<const u64*>(&s_v2[row * S2 + cb + j]);
            float b3 = s_v3[row * S2 + cb + j];
            #pragma unroll
            for (int p = 0; p < 4; p++) {
                int k = j - p;
                if (k >= 0 && k < KS) {
                    int wi = WIDX(k);
                    h1[p] = fma2(wh2[wi], b1, h1[p]);
                    h2[p] = fma2(wh2[wi], b2, h2[p]);
                    h3[p] = fmaf(whs[wi], b3, h3[p]);
                }
            }
        }
        #pragma unroll
        for (int p = 0; p < 4; p++) {
            float mux, muy; unpack2(h1[p], mux, muy);
            float ex2, ey2; unpack2(h2[p], ex2, ey2);
            float exy = h3[p];
            float mux2 = mux * mux, muy2 = muy * muy, muxy = mux * muy;
            float sx = ex2 - mux2, sy = ey2 - muy2, sxy = exy - muxy;
            float num = (2.f * muxy + C1) * (2.f * sxy + C2);
            float den = (mux2 + muy2 + C1) * (sx + sy + C2);
            lsum += __fdividef(num, den);
        }
    }

    // ---- reduction: warp -> block -> slotted global atomic (64-way contention) ----
    #pragma unroll
    for (int o = 16; o > 0; o >>= 1) lsum += __shfl_xor_sync(0xffffffffu, lsum, o);
    __shared__ float wsum[NTHREADS / 32];
    if ((tid & 31) == 0) wsum[tid >> 5] = lsum;
    __syncthreads();
    if (tid == 0) {
        float b = 0.f;
        #pragma unroll
        for (int w = 0; w < NTHREADS / 32; w++) b += wsum[w];
        atomicAdd(&g_slots[blockIdx.y * 8 + blockIdx.x], (double)b);
    }
}

__global__ void finalize_kernel(float* __restrict__ out) {
    int t = threadIdx.x;                     // 128 threads
    double v = g_slots[t];
    g_slots[t] = 0.0;                        // reset for next graph replay
    #pragma unroll
    for (int o = 16; o > 0; o >>= 1) v += __shfl_xor_sync(0xffffffffu, v, o);
    __shared__ double ws[4];
    if ((t & 31) == 0) ws[t >> 5] = v;
    __syncthreads();
    if (t == 0) {
        double total = ws[0] + ws[1] + ws[2] + ws[3];
        out[0] = 1.0f - (float)(total * (1.0 / (32.0 * 2.0 * 512.0 * 512.0)));
    }
}

extern "C" void kernel_launch(void* const* d_in, const int* in_sizes, int n_in,
                              void* d_out, int out_size) {
    const float* x = (const float*)d_in[0];
    const float* y = (const float*)d_in[1];
    const float* kern = (const float*)d_in[2];
    float* out = (float*)d_out;

    dim3 grid(IMG / TW, IMG / TH, 64);
    ssim_main<<<grid, NTHREADS, SMEM_BYTES>>>(x, y, kern);
    finalize_kernel<<<1, NSLOTS>>>(out);
}